// round 1
// baseline (speedup 1.0000x reference)
#include <cuda_runtime.h>
#include <cuda_bf16.h>
#include <cstdint>

// Problem constants
#define BATCH 8
#define NN    2048
#define FF    128

// Scratch (device globals — no allocation allowed)
__device__ float g_r[BATCH * NN];            // 64 KB   : r = (rowsum(adj)+1)^-1/2
__device__ float g_Z[BATCH * NN * FF];       // 8 MB    : Z = r ⊙ (X @ W)

// ---------------------------------------------------------------------------
// Kernel A: row sums of adj (+1 for self loop), r = rsqrt(d)
// One warp per (b, i) row. 8 warps / block -> 2048 blocks.
// ---------------------------------------------------------------------------
__global__ void rowsum_kernel(const float* __restrict__ adj) {
    int gwarp = (blockIdx.x * blockDim.x + threadIdx.x) >> 5;
    int lane  = threadIdx.x & 31;
    if (gwarp >= BATCH * NN) return;
    const float* row = adj + (size_t)gwarp * NN;
    float s = 0.f;
    #pragma unroll
    for (int c = lane * 4; c < NN; c += 32 * 4) {
        float4 v = *(const float4*)(row + c);
        s += (v.x + v.y) + (v.z + v.w);
    }
    #pragma unroll
    for (int o = 16; o; o >>= 1) s += __shfl_xor_sync(0xffffffffu, s, o);
    if (lane == 0) g_r[gwarp] = rsqrtf(s + 1.0f);
}

// ---------------------------------------------------------------------------
// Kernel B: Z[b,m,:] = r[b,m] * (X[b,m,:] @ W)
// Block: 64 rows x 128 cols, BK=32, 256 threads, 4x8 microtile per thread.
// grid (NN/64, BATCH)
// ---------------------------------------------------------------------------
__global__ void xw_kernel(const float* __restrict__ X, const float* __restrict__ W) {
    const int b  = blockIdx.y;
    const int m0 = blockIdx.x * 64;
    __shared__ float Xs[32][68];    // transposed: Xs[k][m]
    __shared__ float Ws[32][128];   // Ws[k][o]

    const int tid = threadIdx.x;
    const int tx  = tid & 15;        // 16 cols of threads
    const int ty  = tid >> 4;        // 16 rows of threads

    float acc[4][8];
    #pragma unroll
    for (int m = 0; m < 4; m++)
        #pragma unroll
        for (int n = 0; n < 8; n++) acc[m][n] = 0.f;

    const float* Xb = X + ((size_t)b * NN + m0) * FF;

    for (int k0 = 0; k0 < FF; k0 += 32) {
        // load X tile 64x32 (transpose into smem)
        #pragma unroll
        for (int t = 0; t < 2; t++) {
            int idx = tid + t * 256;
            int row = idx >> 3, c4 = idx & 7;
            float4 v = *(const float4*)(Xb + (size_t)row * FF + k0 + c4 * 4);
            Xs[c4 * 4 + 0][row] = v.x;
            Xs[c4 * 4 + 1][row] = v.y;
            Xs[c4 * 4 + 2][row] = v.z;
            Xs[c4 * 4 + 3][row] = v.w;
        }
        // load W tile 32x128
        #pragma unroll
        for (int t = 0; t < 4; t++) {
            int idx = tid + t * 256;
            int row = idx >> 5, c4 = idx & 31;
            *(float4*)&Ws[row][c4 * 4] = *(const float4*)(W + (size_t)(k0 + row) * FF + c4 * 4);
        }
        __syncthreads();
        #pragma unroll
        for (int kk = 0; kk < 32; kk++) {
            float4 a  = *(const float4*)&Xs[kk][ty * 4];
            float4 b0 = *(const float4*)&Ws[kk][tx * 4];
            float4 b1 = *(const float4*)&Ws[kk][64 + tx * 4];
            float av[4] = {a.x, a.y, a.z, a.w};
            float bv[8] = {b0.x, b0.y, b0.z, b0.w, b1.x, b1.y, b1.z, b1.w};
            #pragma unroll
            for (int m = 0; m < 4; m++)
                #pragma unroll
                for (int n = 0; n < 8; n++) acc[m][n] += av[m] * bv[n];
        }
        __syncthreads();
    }
    // epilogue: scale by r and store
    #pragma unroll
    for (int m = 0; m < 4; m++) {
        int i = m0 + ty * 4 + m;
        float ri = g_r[b * NN + i];
        float* Zrow = g_Z + ((size_t)b * NN + i) * FF;
        float4 v0 = make_float4(ri * acc[m][0], ri * acc[m][1], ri * acc[m][2], ri * acc[m][3]);
        float4 v1 = make_float4(ri * acc[m][4], ri * acc[m][5], ri * acc[m][6], ri * acc[m][7]);
        *(float4*)(Zrow + tx * 4)      = v0;
        *(float4*)(Zrow + 64 + tx * 4) = v1;
    }
}

// ---------------------------------------------------------------------------
// Kernel C: out[b,i,:] = leaky( r[b,i] * (adj[b,i,:] @ Z[b] + Z[b,i,:]) + bias )
// Block tile: BM=128 x BN=128, BK=32. 256 threads, 8x8 microtile (split 2x2 of 4x4).
// grid (NN/128, BATCH)
// ---------------------------------------------------------------------------
__global__ void __launch_bounds__(256, 2)
spmm_kernel(const float* __restrict__ adj, const float* __restrict__ bias,
            float* __restrict__ out) {
    const int b  = blockIdx.y;
    const int i0 = blockIdx.x * 128;

    __shared__ float As[32][132];   // adj^T tile: As[k][i]
    __shared__ float Bs[32][128];   // Z tile:     Bs[k][o]

    const int tid = threadIdx.x;
    const int tx  = tid & 15;
    const int ty  = tid >> 4;

    float acc[2][2][4][4];
    #pragma unroll
    for (int mi = 0; mi < 2; mi++)
        #pragma unroll
        for (int ni = 0; ni < 2; ni++)
            #pragma unroll
            for (int m = 0; m < 4; m++)
                #pragma unroll
                for (int n = 0; n < 4; n++) acc[mi][ni][m][n] = 0.f;

    const float* adjB = adj + (size_t)b * NN * NN;
    const float* Zb   = g_Z + (size_t)b * NN * FF;

    for (int k0 = 0; k0 < NN; k0 += 32) {
        // load adj tile 128x32, transposed into As[k][i]
        #pragma unroll
        for (int t = 0; t < 4; t++) {
            int idx = tid + t * 256;
            int row = idx >> 3, c4 = idx & 7;
            float4 v = *(const float4*)(adjB + (size_t)(i0 + row) * NN + k0 + c4 * 4);
            As[c4 * 4 + 0][row] = v.x;
            As[c4 * 4 + 1][row] = v.y;
            As[c4 * 4 + 2][row] = v.z;
            As[c4 * 4 + 3][row] = v.w;
        }
        // load Z tile 32x128
        #pragma unroll
        for (int t = 0; t < 4; t++) {
            int idx = tid + t * 256;
            int row = idx >> 5, c4 = idx & 31;
            *(float4*)&Bs[row][c4 * 4] = *(const float4*)(Zb + (size_t)(k0 + row) * FF + c4 * 4);
        }
        __syncthreads();
        #pragma unroll
        for (int kk = 0; kk < 32; kk++) {
            float4 a0 = *(const float4*)&As[kk][ty * 4];
            float4 a1 = *(const float4*)&As[kk][64 + ty * 4];
            float4 b0 = *(const float4*)&Bs[kk][tx * 4];
            float4 b1 = *(const float4*)&Bs[kk][64 + tx * 4];
            float av[2][4] = {{a0.x, a0.y, a0.z, a0.w}, {a1.x, a1.y, a1.z, a1.w}};
            float bv[2][4] = {{b0.x, b0.y, b0.z, b0.w}, {b1.x, b1.y, b1.z, b1.w}};
            #pragma unroll
            for (int mi = 0; mi < 2; mi++)
                #pragma unroll
                for (int m = 0; m < 4; m++)
                    #pragma unroll
                    for (int ni = 0; ni < 2; ni++)
                        #pragma unroll
                        for (int n = 0; n < 4; n++)
                            acc[mi][ni][m][n] += av[mi][m] * bv[ni][n];
        }
        __syncthreads();
    }

    // epilogue: + Z[i] (self loop), * r[i], + bias, leaky relu
    #pragma unroll
    for (int mi = 0; mi < 2; mi++) {
        #pragma unroll
        for (int m = 0; m < 4; m++) {
            int i = i0 + mi * 64 + ty * 4 + m;
            float ri = g_r[b * NN + i];
            const float* Zrow = Zb + (size_t)i * FF;
            float* orow = out + ((size_t)b * NN + i) * FF;
            #pragma unroll
            for (int ni = 0; ni < 2; ni++) {
                int o = ni * 64 + tx * 4;
                float4 z = *(const float4*)(Zrow + o);
                float4 bb = *(const float4*)(bias + o);
                float4 v;
                v.x = (acc[mi][ni][m][0] + z.x) * ri + bb.x;
                v.y = (acc[mi][ni][m][1] + z.y) * ri + bb.y;
                v.z = (acc[mi][ni][m][2] + z.z) * ri + bb.z;
                v.w = (acc[mi][ni][m][3] + z.w) * ri + bb.w;
                v.x = v.x > 0.f ? v.x : 0.01f * v.x;
                v.y = v.y > 0.f ? v.y : 0.01f * v.y;
                v.z = v.z > 0.f ? v.z : 0.01f * v.z;
                v.w = v.w > 0.f ? v.w : 0.01f * v.w;
                *(float4*)(orow + o) = v;
            }
        }
    }
}

// ---------------------------------------------------------------------------
extern "C" void kernel_launch(void* const* d_in, const int* in_sizes, int n_in,
                              void* d_out, int out_size) {
    const float* X    = (const float*)d_in[0];   // [8, 2048, 128]
    const float* adj  = (const float*)d_in[1];   // [8, 2048, 2048]
    const float* W    = (const float*)d_in[2];   // [128, 128]
    const float* bias = (const float*)d_in[3];   // [128]
    float* out = (float*)d_out;                  // [8, 2048, 128]

    // A: degrees -> r
    rowsum_kernel<<<(BATCH * NN) / 8, 256>>>(adj);
    // B: Z = r ⊙ (X @ W)
    xw_kernel<<<dim3(NN / 64, BATCH), 256>>>(X, W);
    // C: out = leaky(r ⊙ (adj @ Z + Z) + bias)
    spmm_kernel<<<dim3(NN / 128, BATCH), 256>>>(adj, bias, out);
}

// round 3
// speedup vs baseline: 2.9277x; 2.9277x over previous
#include <cuda_runtime.h>
#include <cuda_fp16.h>
#include <cstdint>

#define BATCH 8
#define NN    2048
#define FF    128

// Scratch (device globals — allocation is forbidden)
__device__ float  g_r[BATCH * NN];                       // 64 KB
__device__ float  g_Z[BATCH * NN * FF];                  // 8 MB  : Z = r ⊙ (XW), fp32 (self-loop term)
__device__ __half g_Zh[BATCH * FF * NN];                 // 8 MB  : Z transposed [b][o][j], fp16
__device__ __half g_adjh[(size_t)BATCH * NN * NN];       // 64 MB : adj in fp16

// ---------------------------------------------------------------------------
// Kernel A: row sums of adj (+1 self loop) -> r = rsqrt(d); also convert adj->fp16
// One warp per (b,i) row.
// ---------------------------------------------------------------------------
__global__ void rowsum_cvt_kernel(const float* __restrict__ adj) {
    int gwarp = (blockIdx.x * blockDim.x + threadIdx.x) >> 5;
    int lane  = threadIdx.x & 31;
    const float* row = adj + (size_t)gwarp * NN;
    __half* hrow = g_adjh + (size_t)gwarp * NN;
    float s = 0.f;
    #pragma unroll
    for (int c = lane * 4; c < NN; c += 32 * 4) {
        float4 v = *(const float4*)(row + c);
        s += (v.x + v.y) + (v.z + v.w);
        __half2 h0 = __floats2half2_rn(v.x, v.y);
        __half2 h1 = __floats2half2_rn(v.z, v.w);
        uint2 u;
        u.x = reinterpret_cast<unsigned&>(h0);
        u.y = reinterpret_cast<unsigned&>(h1);
        *(uint2*)(hrow + c) = u;
    }
    #pragma unroll
    for (int o = 16; o; o >>= 1) s += __shfl_xor_sync(0xffffffffu, s, o);
    if (lane == 0) g_r[gwarp] = rsqrtf(s + 1.0f);
}

// ---------------------------------------------------------------------------
// Kernel B: Z = r ⊙ (X @ W). Writes fp32 [j][o] and fp16 transposed [o][j].
// Block: 64 rows x 128 cols, BK=32, 256 threads, 4x8 microtile.
// ---------------------------------------------------------------------------
__global__ void xw_kernel(const float* __restrict__ X, const float* __restrict__ W) {
    const int b  = blockIdx.y;
    const int m0 = blockIdx.x * 64;
    __shared__ float Xs[32][68];
    __shared__ float Ws[32][128];

    const int tid = threadIdx.x;
    const int tx  = tid & 15;
    const int ty  = tid >> 4;

    float acc[4][8];
    #pragma unroll
    for (int m = 0; m < 4; m++)
        #pragma unroll
        for (int n = 0; n < 8; n++) acc[m][n] = 0.f;

    const float* Xb = X + ((size_t)b * NN + m0) * FF;

    for (int k0 = 0; k0 < FF; k0 += 32) {
        #pragma unroll
        for (int t = 0; t < 2; t++) {
            int idx = tid + t * 256;
            int row = idx >> 3, c4 = idx & 7;
            float4 v = *(const float4*)(Xb + (size_t)row * FF + k0 + c4 * 4);
            Xs[c4 * 4 + 0][row] = v.x;
            Xs[c4 * 4 + 1][row] = v.y;
            Xs[c4 * 4 + 2][row] = v.z;
            Xs[c4 * 4 + 3][row] = v.w;
        }
        #pragma unroll
        for (int t = 0; t < 4; t++) {
            int idx = tid + t * 256;
            int row = idx >> 5, c4 = idx & 31;
            *(float4*)&Ws[row][c4 * 4] = *(const float4*)(W + (size_t)(k0 + row) * FF + c4 * 4);
        }
        __syncthreads();
        #pragma unroll
        for (int kk = 0; kk < 32; kk++) {
            float4 a  = *(const float4*)&Xs[kk][ty * 4];
            float4 b0 = *(const float4*)&Ws[kk][tx * 4];
            float4 b1 = *(const float4*)&Ws[kk][64 + tx * 4];
            float av[4] = {a.x, a.y, a.z, a.w};
            float bv[8] = {b0.x, b0.y, b0.z, b0.w, b1.x, b1.y, b1.z, b1.w};
            #pragma unroll
            for (int m = 0; m < 4; m++)
                #pragma unroll
                for (int n = 0; n < 8; n++) acc[m][n] += av[m] * bv[n];
        }
        __syncthreads();
    }

    const int j0 = m0 + ty * 4;
    float r4[4];
    #pragma unroll
    for (int m = 0; m < 4; m++) r4[m] = g_r[b * NN + j0 + m];

    // fp32 Z [j][o]
    #pragma unroll
    for (int m = 0; m < 4; m++) {
        float* Zrow = g_Z + ((size_t)b * NN + j0 + m) * FF;
        float4 v0 = make_float4(r4[m]*acc[m][0], r4[m]*acc[m][1], r4[m]*acc[m][2], r4[m]*acc[m][3]);
        float4 v1 = make_float4(r4[m]*acc[m][4], r4[m]*acc[m][5], r4[m]*acc[m][6], r4[m]*acc[m][7]);
        *(float4*)(Zrow + tx * 4)      = v0;
        *(float4*)(Zrow + 64 + tx * 4) = v1;
    }
    // fp16 Z transposed [o][j]
    __half* ZhB = g_Zh + (size_t)b * FF * NN;
    #pragma unroll
    for (int n = 0; n < 8; n++) {
        int o = (n < 4) ? (tx * 4 + n) : (64 + tx * 4 + (n - 4));
        __half2 p0 = __floats2half2_rn(r4[0]*acc[0][n], r4[1]*acc[1][n]);
        __half2 p1 = __floats2half2_rn(r4[2]*acc[2][n], r4[3]*acc[3][n]);
        uint2 u;
        u.x = reinterpret_cast<unsigned&>(p0);
        u.y = reinterpret_cast<unsigned&>(p1);
        *(uint2*)(ZhB + (size_t)o * NN + j0) = u;
    }
}

// ---------------------------------------------------------------------------
// Kernel C: tensor-core GEMM.  out[b,i,o] = leaky( r_i*(adj[i,:]@Z + Z_i) + bias )
// BM=128, BN=128, BK=32. 8 warps (2x4), warp tile 64x32. m16n8k16 fp16 mma.
// 2-stage cp.async pipeline; ldmatrix fragment loads (pad-40 stride, conflict-free).
// ---------------------------------------------------------------------------
#define BK   32
#define KPAD 40

__global__ void __launch_bounds__(256)
gcn_mma_kernel(const float* __restrict__ bias, float* __restrict__ out) {
    const int b  = blockIdx.y;
    const int i0 = blockIdx.x * 128;

    __shared__ __half As[2][128 * KPAD];
    __shared__ __half Bs[2][128 * KPAD];

    const int tid  = threadIdx.x;
    const int warp = tid >> 5, lane = tid & 31;
    const int wm   = warp >> 2, wn = warp & 3;   // 2 x 4 warps
    const int g    = lane >> 2, tig = lane & 3;
    const int lm   = lane >> 3;                  // ldmatrix: matrix index 0..3
    const int lr   = lane & 7;                   // ldmatrix: row within matrix

    const __half* adjB = g_adjh + (size_t)b * NN * NN;
    const __half* ZhB  = g_Zh   + (size_t)b * FF * NN;

    float acc[4][4][4];
    #pragma unroll
    for (int mt = 0; mt < 4; mt++)
        #pragma unroll
        for (int nt = 0; nt < 4; nt++)
            #pragma unroll
            for (int q = 0; q < 4; q++) acc[mt][nt][q] = 0.f;

    // stage loader: 256 threads * 2 chunks of 16B each for A and for B
    const int lrow = tid >> 2;          // 0..63
    const int lc   = tid & 3;           // chunk
    #define LOAD_STAGE(st, k0)                                                        \
    {                                                                                 \
        _Pragma("unroll")                                                             \
        for (int t = 0; t < 2; t++) {                                                 \
            int row = lrow + t * 64;                                                  \
            uint32_t sa = (uint32_t)__cvta_generic_to_shared(                         \
                &As[st][row * KPAD + lc * 8]);                                        \
            const void* ga = adjB + (size_t)(i0 + row) * NN + (k0) + lc * 8;          \
            asm volatile("cp.async.cg.shared.global [%0], [%1], 16;\n"                \
                         :: "r"(sa), "l"(ga));                                        \
            uint32_t sb = (uint32_t)__cvta_generic_to_shared(                         \
                &Bs[st][row * KPAD + lc * 8]);                                        \
            const void* gb = ZhB + (size_t)row * NN + (k0) + lc * 8;                  \
            asm volatile("cp.async.cg.shared.global [%0], [%1], 16;\n"                \
                         :: "r"(sb), "l"(gb));                                        \
        }                                                                             \
        asm volatile("cp.async.commit_group;\n");                                     \
    }

    LOAD_STAGE(0, 0);
    const int NIT = NN / BK;   // 64
    for (int it = 0; it < NIT; it++) {
        if (it + 1 < NIT) {
            LOAD_STAGE((it + 1) & 1, (it + 1) * BK);
            asm volatile("cp.async.wait_group 1;\n");
        } else {
            asm volatile("cp.async.wait_group 0;\n");
        }
        __syncthreads();
        const __half* Asb = As[it & 1];
        const __half* Bsb = Bs[it & 1];

        #pragma unroll
        for (int ks = 0; ks < 2; ks++) {
            const int kb = ks * 16;

            uint32_t af[4][4];
            #pragma unroll
            for (int mt = 0; mt < 4; mt++) {
                uint32_t addr = (uint32_t)__cvta_generic_to_shared(
                    &Asb[(wm * 64 + mt * 16 + (lm & 1) * 8 + lr) * KPAD + kb + (lm >> 1) * 8]);
                asm volatile("ldmatrix.sync.aligned.m8n8.x4.shared.b16 {%0,%1,%2,%3}, [%4];\n"
                             : "=r"(af[mt][0]), "=r"(af[mt][1]), "=r"(af[mt][2]), "=r"(af[mt][3])
                             : "r"(addr));
            }
            uint32_t bf[4][2];
            #pragma unroll
            for (int np = 0; np < 2; np++) {
                uint32_t addr = (uint32_t)__cvta_generic_to_shared(
                    &Bsb[(wn * 32 + (np * 2 + (lm >> 1)) * 8 + lr) * KPAD + kb + (lm & 1) * 8]);
                uint32_t t0, t1, t2, t3;
                asm volatile("ldmatrix.sync.aligned.m8n8.x4.shared.b16 {%0,%1,%2,%3}, [%4];\n"
                             : "=r"(t0), "=r"(t1), "=r"(t2), "=r"(t3) : "r"(addr));
                bf[np * 2][0]     = t0; bf[np * 2][1]     = t1;
                bf[np * 2 + 1][0] = t2; bf[np * 2 + 1][1] = t3;
            }
            #pragma unroll
            for (int mt = 0; mt < 4; mt++)
                #pragma unroll
                for (int nt = 0; nt < 4; nt++)
                    asm volatile("mma.sync.aligned.m16n8k16.row.col.f32.f16.f16.f32 "
                                 "{%0,%1,%2,%3}, {%4,%5,%6,%7}, {%8,%9}, {%0,%1,%2,%3};\n"
                                 : "+f"(acc[mt][nt][0]), "+f"(acc[mt][nt][1]),
                                   "+f"(acc[mt][nt][2]), "+f"(acc[mt][nt][3])
                                 : "r"(af[mt][0]), "r"(af[mt][1]), "r"(af[mt][2]), "r"(af[mt][3]),
                                   "r"(bf[nt][0]), "r"(bf[nt][1]));
        }
        __syncthreads();
    }

    // epilogue: + Z_i (self loop), * r_i, + bias, leaky relu
    const float* Zb = g_Z + (size_t)b * NN * FF;
    #pragma unroll
    for (int mt = 0; mt < 4; mt++) {
        #pragma unroll
        for (int h = 0; h < 2; h++) {
            const int i = i0 + wm * 64 + mt * 16 + g + h * 8;
            const float ri = g_r[b * NN + i];
            const float* Zrow = Zb + (size_t)i * FF;
            float* orow = out + ((size_t)b * NN + i) * FF;
            #pragma unroll
            for (int nt = 0; nt < 4; nt++) {
                const int o = wn * 32 + nt * 8 + tig * 2;
                float2 z  = *(const float2*)(Zrow + o);
                float2 bb = *(const float2*)(bias + o);
                float v0 = (acc[mt][nt][h * 2 + 0] + z.x) * ri + bb.x;
                float v1 = (acc[mt][nt][h * 2 + 1] + z.y) * ri + bb.y;
                v0 = v0 > 0.f ? v0 : 0.01f * v0;
                v1 = v1 > 0.f ? v1 : 0.01f * v1;
                *(float2*)(orow + o) = make_float2(v0, v1);
            }
        }
    }
}

// ---------------------------------------------------------------------------
extern "C" void kernel_launch(void* const* d_in, const int* in_sizes, int n_in,
                              void* d_out, int out_size) {
    const float* X    = (const float*)d_in[0];   // [8, 2048, 128]
    const float* adj  = (const float*)d_in[1];   // [8, 2048, 2048]
    const float* W    = (const float*)d_in[2];   // [128, 128]
    const float* bias = (const float*)d_in[3];   // [128]
    float* out = (float*)d_out;                  // [8, 2048, 128]

    rowsum_cvt_kernel<<<(BATCH * NN) / 8, 256>>>(adj);
    xw_kernel<<<dim3(NN / 64, BATCH), 256>>>(X, W);
    gcn_mma_kernel<<<dim3(NN / 128, BATCH), 256>>>(bias, out);
}

// round 7
// speedup vs baseline: 3.0868x; 1.0543x over previous
#include <cuda_runtime.h>
#include <cuda_fp16.h>
#include <cstdint>

#define BATCH 8
#define NN    2048
#define FF    128

// Scratch (device globals — allocation is forbidden)
__device__ float  g_r[BATCH * NN];                       // 64 KB
__device__ float  g_Z[BATCH * NN * FF];                  // 8 MB  : Z = r ⊙ (XW), fp32 (self-loop term)
__device__ __half g_Zh[BATCH * FF * NN];                 // 4 MB  : Z transposed [b][o][j], fp16 (GEMM B)
__device__ __half g_adjh[(size_t)BATCH * NN * NN];       // 64 MB : adj in fp16 (GEMM A)

// ---------------------------------------------------------------------------
// Kernel A: row sums of adj (+1 self loop) -> r = rsqrt(d); also convert adj->fp16
// ---------------------------------------------------------------------------
__global__ void rowsum_cvt_kernel(const float* __restrict__ adj) {
    int gwarp = (blockIdx.x * blockDim.x + threadIdx.x) >> 5;
    int lane  = threadIdx.x & 31;
    const float* row = adj + (size_t)gwarp * NN;
    __half* hrow = g_adjh + (size_t)gwarp * NN;
    float s = 0.f;
    #pragma unroll
    for (int c = lane * 4; c < NN; c += 32 * 4) {
        float4 v = *(const float4*)(row + c);
        s += (v.x + v.y) + (v.z + v.w);
        __half2 h0 = __floats2half2_rn(v.x, v.y);
        __half2 h1 = __floats2half2_rn(v.z, v.w);
        uint2 u;
        u.x = reinterpret_cast<unsigned&>(h0);
        u.y = reinterpret_cast<unsigned&>(h1);
        *(uint2*)(hrow + c) = u;
    }
    #pragma unroll
    for (int o = 16; o; o >>= 1) s += __shfl_xor_sync(0xffffffffu, s, o);
    if (lane == 0) g_r[gwarp] = rsqrtf(s + 1.0f);
}

// ---------------------------------------------------------------------------
// Kernel B: Z = r ⊙ (X @ W). Writes fp32 [j][o] and fp16 transposed [o][j].
// ---------------------------------------------------------------------------
__global__ void xw_kernel(const float* __restrict__ X, const float* __restrict__ W) {
    const int b  = blockIdx.y;
    const int m0 = blockIdx.x * 64;
    __shared__ float Xs[32][68];
    __shared__ float Ws[32][128];

    const int tid = threadIdx.x;
    const int tx  = tid & 15;
    const int ty  = tid >> 4;

    float acc[4][8];
    #pragma unroll
    for (int m = 0; m < 4; m++)
        #pragma unroll
        for (int n = 0; n < 8; n++) acc[m][n] = 0.f;

    const float* Xb = X + ((size_t)b * NN + m0) * FF;

    for (int k0 = 0; k0 < FF; k0 += 32) {
        #pragma unroll
        for (int t = 0; t < 2; t++) {
            int idx = tid + t * 256;
            int row = idx >> 3, c4 = idx & 7;
            float4 v = *(const float4*)(Xb + (size_t)row * FF + k0 + c4 * 4);
            Xs[c4 * 4 + 0][row] = v.x;
            Xs[c4 * 4 + 1][row] = v.y;
            Xs[c4 * 4 + 2][row] = v.z;
            Xs[c4 * 4 + 3][row] = v.w;
        }
        #pragma unroll
        for (int t = 0; t < 4; t++) {
            int idx = tid + t * 256;
            int row = idx >> 5, c4 = idx & 31;
            *(float4*)&Ws[row][c4 * 4] = *(const float4*)(W + (size_t)(k0 + row) * FF + c4 * 4);
        }
        __syncthreads();
        #pragma unroll
        for (int kk = 0; kk < 32; kk++) {
            float4 a  = *(const float4*)&Xs[kk][ty * 4];
            float4 b0 = *(const float4*)&Ws[kk][tx * 4];
            float4 b1 = *(const float4*)&Ws[kk][64 + tx * 4];
            float av[4] = {a.x, a.y, a.z, a.w};
            float bv[8] = {b0.x, b0.y, b0.z, b0.w, b1.x, b1.y, b1.z, b1.w};
            #pragma unroll
            for (int m = 0; m < 4; m++)
                #pragma unroll
                for (int n = 0; n < 8; n++) acc[m][n] += av[m] * bv[n];
        }
        __syncthreads();
    }

    const int j0 = m0 + ty * 4;
    float r4[4];
    #pragma unroll
    for (int m = 0; m < 4; m++) r4[m] = g_r[b * NN + j0 + m];

    #pragma unroll
    for (int m = 0; m < 4; m++) {
        float* Zrow = g_Z + ((size_t)b * NN + j0 + m) * FF;
        float4 v0 = make_float4(r4[m]*acc[m][0], r4[m]*acc[m][1], r4[m]*acc[m][2], r4[m]*acc[m][3]);
        float4 v1 = make_float4(r4[m]*acc[m][4], r4[m]*acc[m][5], r4[m]*acc[m][6], r4[m]*acc[m][7]);
        *(float4*)(Zrow + tx * 4)      = v0;
        *(float4*)(Zrow + 64 + tx * 4) = v1;
    }
    __half* ZhB = g_Zh + (size_t)b * FF * NN;
    #pragma unroll
    for (int n = 0; n < 8; n++) {
        int o = (n < 4) ? (tx * 4 + n) : (64 + tx * 4 + (n - 4));
        __half2 p0 = __floats2half2_rn(r4[0]*acc[0][n], r4[1]*acc[1][n]);
        __half2 p1 = __floats2half2_rn(r4[2]*acc[2][n], r4[3]*acc[3][n]);
        uint2 u;
        u.x = reinterpret_cast<unsigned&>(p0);
        u.y = reinterpret_cast<unsigned&>(p1);
        *(uint2*)(ZhB + (size_t)o * NN + j0) = u;
    }
}

// ---------------------------------------------------------------------------
// Kernel C: mma.sync GEMM.  out[b,i,o] = leaky( r_i*(adj[i,:]@Z + Z_i) + bias )
// BM=64, BN=128, BK=32. Grid 256 CTAs (32 x 8) -> 2 CTAs/SM. 8 warps (2x4),
// warp tile 32x32. 3-stage cp.async pipeline. 45KB STATIC smem (<=48KB, no
// cudaFuncSetAttribute / dynamic smem anywhere).
// ---------------------------------------------------------------------------
#define BK      32
#define STAGES  3
#define NIT     (NN / BK)              // 64
#define RPAD    40                     // halves per row (80 B) — conflict-free (R3-proven)
#define A_HALF  (64  * RPAD)           // 2560 halves = 5120 B
#define B_HALF  (128 * RPAD)           // 5120 halves = 10240 B
#define STG_HALF (A_HALF + B_HALF)     // 7680 halves = 15360 B

__global__ void __launch_bounds__(256, 2)
gcn_mma_kernel(const float* __restrict__ bias, float* __restrict__ out) {
    __shared__ __half smem[STAGES * STG_HALF];   // 46080 B static

    const int b  = blockIdx.y;
    const int i0 = blockIdx.x * 64;

    const int tid  = threadIdx.x;
    const int warp = tid >> 5, lane = tid & 31;
    const int wm   = warp >> 2, wn = warp & 3;   // 2 x 4 warps, warp tile 32x32
    const int g    = lane >> 2, tig = lane & 3;
    const int lm   = lane >> 3;                  // ldmatrix: matrix index 0..3
    const int lr   = lane & 7;                   // ldmatrix: row within matrix

    const __half* adjB = g_adjh + (size_t)b * NN * NN + (size_t)i0 * NN;
    const __half* ZhB  = g_Zh   + (size_t)b * FF * NN;

    float acc[2][4][4];
    #pragma unroll
    for (int mt = 0; mt < 2; mt++)
        #pragma unroll
        for (int nt = 0; nt < 4; nt++)
            #pragma unroll
            for (int q = 0; q < 4; q++) acc[mt][nt][q] = 0.f;

    // stage loader: A = 256 chunks of 16B (1/thread), B = 512 chunks (2/thread)
    #define LOAD_STAGE(s, k0)                                                     \
    {                                                                             \
        __half* sA = smem + (s) * STG_HALF;                                       \
        __half* sB = sA + A_HALF;                                                 \
        {                                                                         \
            int row = tid >> 2, c = tid & 3;                                      \
            uint32_t d = (uint32_t)__cvta_generic_to_shared(sA + row * RPAD + c * 8); \
            const void* gp = adjB + (size_t)row * NN + (k0) + c * 8;              \
            asm volatile("cp.async.cg.shared.global [%0], [%1], 16;\n"            \
                         :: "r"(d), "l"(gp));                                     \
        }                                                                         \
        _Pragma("unroll")                                                         \
        for (int t = 0; t < 2; t++) {                                             \
            int idx = tid + t * 256;                                              \
            int row = idx >> 2, c = idx & 3;                                      \
            uint32_t d = (uint32_t)__cvta_generic_to_shared(sB + row * RPAD + c * 8); \
            const void* gp = ZhB + (size_t)row * NN + (k0) + c * 8;               \
            asm volatile("cp.async.cg.shared.global [%0], [%1], 16;\n"            \
                         :: "r"(d), "l"(gp));                                     \
        }                                                                         \
        asm volatile("cp.async.commit_group;\n");                                 \
    }

    // prologue: stages 0,1
    LOAD_STAGE(0, 0);
    LOAD_STAGE(1, BK);

    for (int i = 0; i < NIT; i++) {
        asm volatile("cp.async.wait_group 1;\n");
        __syncthreads();

        // prefetch stage i+2 (slot (i+2)%3 == slot consumed at iter i-1, safe
        // because end-of-iter sync at i-1 drained its readers)
        if (i + 2 < NIT) {
            LOAD_STAGE((i + 2) % STAGES, (i + 2) * BK);
        } else {
            asm volatile("cp.async.commit_group;\n");
        }

        const __half* Asb = smem + (i % STAGES) * STG_HALF;
        const __half* Bsb = Asb + A_HALF;

        #pragma unroll
        for (int ks = 0; ks < 2; ks++) {
            const int kb = ks * 16;
            uint32_t af[2][4];
            #pragma unroll
            for (int mt = 0; mt < 2; mt++) {
                uint32_t addr = (uint32_t)__cvta_generic_to_shared(
                    &Asb[(wm * 32 + mt * 16 + (lm & 1) * 8 + lr) * RPAD + kb + (lm >> 1) * 8]);
                asm volatile("ldmatrix.sync.aligned.m8n8.x4.shared.b16 {%0,%1,%2,%3}, [%4];\n"
                             : "=r"(af[mt][0]), "=r"(af[mt][1]), "=r"(af[mt][2]), "=r"(af[mt][3])
                             : "r"(addr));
            }
            uint32_t bf[4][2];
            #pragma unroll
            for (int np = 0; np < 2; np++) {
                uint32_t addr = (uint32_t)__cvta_generic_to_shared(
                    &Bsb[(wn * 32 + (np * 2 + (lm >> 1)) * 8 + lr) * RPAD + kb + (lm & 1) * 8]);
                uint32_t t0, t1, t2, t3;
                asm volatile("ldmatrix.sync.aligned.m8n8.x4.shared.b16 {%0,%1,%2,%3}, [%4];\n"
                             : "=r"(t0), "=r"(t1), "=r"(t2), "=r"(t3) : "r"(addr));
                bf[np * 2][0]     = t0; bf[np * 2][1]     = t1;
                bf[np * 2 + 1][0] = t2; bf[np * 2 + 1][1] = t3;
            }
            #pragma unroll
            for (int mt = 0; mt < 2; mt++)
                #pragma unroll
                for (int nt = 0; nt < 4; nt++)
                    asm volatile("mma.sync.aligned.m16n8k16.row.col.f32.f16.f16.f32 "
                                 "{%0,%1,%2,%3}, {%4,%5,%6,%7}, {%8,%9}, {%0,%1,%2,%3};\n"
                                 : "+f"(acc[mt][nt][0]), "+f"(acc[mt][nt][1]),
                                   "+f"(acc[mt][nt][2]), "+f"(acc[mt][nt][3])
                                 : "r"(af[mt][0]), "r"(af[mt][1]), "r"(af[mt][2]), "r"(af[mt][3]),
                                   "r"(bf[nt][0]), "r"(bf[nt][1]));
        }
        __syncthreads();
    }

    // epilogue: + Z_i (self loop), * r_i, + bias, leaky relu
    const float* Zb = g_Z + (size_t)b * NN * FF;
    #pragma unroll
    for (int mt = 0; mt < 2; mt++) {
        #pragma unroll
        for (int h = 0; h < 2; h++) {
            const int i = i0 + wm * 32 + mt * 16 + g + h * 8;
            const float ri = g_r[b * NN + i];
            const float* Zrow = Zb + (size_t)i * FF;
            float* orow = out + ((size_t)b * NN + i) * FF;
            #pragma unroll
            for (int nt = 0; nt < 4; nt++) {
                const int o = wn * 32 + nt * 8 + tig * 2;
                float2 z  = *(const float2*)(Zrow + o);
                float2 bb = *(const float2*)(bias + o);
                float v0 = (acc[mt][nt][h * 2 + 0] + z.x) * ri + bb.x;
                float v1 = (acc[mt][nt][h * 2 + 1] + z.y) * ri + bb.y;
                v0 = v0 > 0.f ? v0 : 0.01f * v0;
                v1 = v1 > 0.f ? v1 : 0.01f * v1;
                *(float2*)(orow + o) = make_float2(v0, v1);
            }
        }
    }
}

// ---------------------------------------------------------------------------
extern "C" void kernel_launch(void* const* d_in, const int* in_sizes, int n_in,
                              void* d_out, int out_size) {
    const float* X    = (const float*)d_in[0];   // [8, 2048, 128]
    const float* adj  = (const float*)d_in[1];   // [8, 2048, 2048]
    const float* W    = (const float*)d_in[2];   // [128, 128]
    const float* bias = (const float*)d_in[3];   // [128]
    float* out = (float*)d_out;                  // [8, 2048, 128]

    rowsum_cvt_kernel<<<(BATCH * NN) / 8, 256>>>(adj);
    xw_kernel<<<dim3(NN / 64, BATCH), 256>>>(X, W);
    gcn_mma_kernel<<<dim3(NN / 64, BATCH), 256>>>(bias, out);
}